// round 2
// baseline (speedup 1.0000x reference)
#include <cuda_runtime.h>
#include <cuda_bf16.h>
#include <math.h>

// Problem constants
#define BATCH 4
#define CH    256
#define HW    4096   // 64*64
#define GROUPS 8
#define CPG   (CH / GROUPS)   // 32
#define EPS   1e-5f

// ---------------------------------------------------------------------------
// Scratch (device globals — no allocations allowed)
// ---------------------------------------------------------------------------
__device__ float g_xn[(size_t)BATCH * CH * HW];
__device__ float g_q [(size_t)BATCH * CH * HW];
__device__ float g_k [(size_t)BATCH * CH * HW];
__device__ float g_v [(size_t)BATCH * CH * HW];
__device__ float g_ao[(size_t)BATCH * CH * HW];
__device__ float g_s [(size_t)BATCH * HW * HW];   // 268 MB attention logits/probs

// ---------------------------------------------------------------------------
// GroupNorm: one block per (batch, group). Reduces 32*4096 = 131072 floats.
// ---------------------------------------------------------------------------
__global__ void gn_kernel(const float* __restrict__ x,
                          const float* __restrict__ gamma,
                          const float* __restrict__ beta,
                          float* __restrict__ xn) {
    const int bg = blockIdx.x;
    const int b = bg >> 3;
    const int g = bg & 7;
    const size_t base = ((size_t)b * CH + (size_t)g * CPG) * HW;
    const int n = CPG * HW;  // 131072

    float s = 0.f, ss = 0.f;
    for (int i = threadIdx.x; i < n; i += 256) {
        float v = x[base + i];
        s += v; ss += v * v;
    }
    // warp reduce
    #pragma unroll
    for (int o = 16; o > 0; o >>= 1) {
        s  += __shfl_down_sync(0xffffffffu, s,  o);
        ss += __shfl_down_sync(0xffffffffu, ss, o);
    }
    __shared__ float sh[18];
    const int warp = threadIdx.x >> 5, lane = threadIdx.x & 31;
    if (lane == 0) { sh[warp] = s; sh[warp + 8] = ss; }
    __syncthreads();
    if (threadIdx.x == 0) {
        float S = 0.f, SS = 0.f;
        #pragma unroll
        for (int i = 0; i < 8; i++) { S += sh[i]; SS += sh[i + 8]; }
        float mean = S / (float)n;
        float var  = SS / (float)n - mean * mean;
        sh[16] = mean;
        sh[17] = rsqrtf(var + EPS);
    }
    __syncthreads();
    const float mean = sh[16], inv = sh[17];
    for (int i = threadIdx.x; i < n; i += 256) {
        int c = g * CPG + (i >> 12);   // i / 4096
        xn[base + i] = (x[base + i] - mean) * inv * gamma[c] + beta[c];
    }
}

// ---------------------------------------------------------------------------
// Generic strided SGEMM:
//   C[m, n] = alpha * sum_k A[m*as_m + k*as_k] * B[k*bs_k + n*bs_n]
//             (+ bias[m]) (+ res[m*N + n])
// C row-major with leading dim N. Per-batch pointer strides via blockIdx.z.
// Tile: BM=BN=64, BK=16, 256 threads, 4x4 register tile per thread.
// M % 64 == 0, N % 64 == 0, K % 16 == 0 are guaranteed by the problem sizes.
// ---------------------------------------------------------------------------
#define BM 64
#define BN 64
#define BK 16
__global__ __launch_bounds__(256)
void gemm_kernel(const float* __restrict__ A, const float* __restrict__ B,
                 float* __restrict__ C,
                 const float* __restrict__ bias, const float* __restrict__ res,
                 int M, int N, int K,
                 long as_m, long as_k, long bs_k, long bs_n,
                 long aB, long bB, long cB, long rB, float alpha) {
    const int bz = blockIdx.z;
    A += (long)bz * aB;
    B += (long)bz * bB;
    C += (long)bz * cB;
    if (res) res += (long)bz * rB;

    __shared__ float As[BK][BM + 1];
    __shared__ float Bs[BK][BN + 1];

    const int tid = threadIdx.x;
    const int m0 = blockIdx.y * BM;
    const int n0 = blockIdx.x * BN;
    const int tr = tid >> 4;    // 0..15
    const int tc = tid & 15;    // 0..15

    float acc[4][4] = {};

    for (int k0 = 0; k0 < K; k0 += BK) {
        // ---- load A tile (BM x BK = 1024 elems, 4 per thread) ----
        if (as_k == 1) {
            // k is the unit-stride dim: make k fast-varying for coalescing
            #pragma unroll
            for (int r = 0; r < 4; r++) {
                int i = tid + r * 256;
                int k = i & (BK - 1);
                int m = i >> 4;
                As[k][m] = A[(long)(m0 + m) * as_m + (long)(k0 + k) * as_k];
            }
        } else {
            // m is (hopefully) the unit-stride dim
            #pragma unroll
            for (int r = 0; r < 4; r++) {
                int i = tid + r * 256;
                int m = i & (BM - 1);
                int k = i >> 6;
                As[k][m] = A[(long)(m0 + m) * as_m + (long)(k0 + k) * as_k];
            }
        }
        // ---- load B tile (BK x BN = 1024 elems) ----
        if (bs_n == 1) {
            #pragma unroll
            for (int r = 0; r < 4; r++) {
                int i = tid + r * 256;
                int n = i & (BN - 1);
                int k = i >> 6;
                Bs[k][n] = B[(long)(k0 + k) * bs_k + (long)(n0 + n) * bs_n];
            }
        } else {
            #pragma unroll
            for (int r = 0; r < 4; r++) {
                int i = tid + r * 256;
                int k = i & (BK - 1);
                int n = i >> 4;
                Bs[k][n] = B[(long)(k0 + k) * bs_k + (long)(n0 + n) * bs_n];
            }
        }
        __syncthreads();

        #pragma unroll
        for (int k = 0; k < BK; k++) {
            float a[4], bvv[4];
            #pragma unroll
            for (int i = 0; i < 4; i++) a[i]   = As[k][tr + i * 16];
            #pragma unroll
            for (int j = 0; j < 4; j++) bvv[j] = Bs[k][tc + j * 16];
            #pragma unroll
            for (int i = 0; i < 4; i++)
                #pragma unroll
                for (int j = 0; j < 4; j++)
                    acc[i][j] += a[i] * bvv[j];
        }
        __syncthreads();
    }

    #pragma unroll
    for (int i = 0; i < 4; i++) {
        const int m = m0 + tr + i * 16;
        const float bval = bias ? bias[m] : 0.f;
        #pragma unroll
        for (int j = 0; j < 4; j++) {
            const int n = n0 + tc + j * 16;
            float v = acc[i][j] * alpha + bval;
            if (res) v += res[(long)m * N + n];
            C[(long)m * N + n] = v;
        }
    }
}

// ---------------------------------------------------------------------------
// Row softmax over rows of length 4096, in place. One block per row.
// ---------------------------------------------------------------------------
__global__ __launch_bounds__(256)
void softmax_kernel(float* __restrict__ S) {
    float* p = S + (size_t)blockIdx.x * HW;
    const int tid = threadIdx.x;

    float m = -INFINITY;
    for (int i = tid; i < HW; i += 256) m = fmaxf(m, p[i]);
    #pragma unroll
    for (int o = 16; o > 0; o >>= 1) m = fmaxf(m, __shfl_xor_sync(0xffffffffu, m, o));
    __shared__ float sha[8], shb[8];
    if ((tid & 31) == 0) sha[tid >> 5] = m;
    __syncthreads();
    float rm = sha[0];
    #pragma unroll
    for (int i = 1; i < 8; i++) rm = fmaxf(rm, sha[i]);

    float sum = 0.f;
    for (int i = tid; i < HW; i += 256) {
        float e = __expf(p[i] - rm);
        p[i] = e;
        sum += e;
    }
    #pragma unroll
    for (int o = 16; o > 0; o >>= 1) sum += __shfl_xor_sync(0xffffffffu, sum, o);
    if ((tid & 31) == 0) shb[tid >> 5] = sum;
    __syncthreads();
    float tot = 0.f;
    #pragma unroll
    for (int i = 0; i < 8; i++) tot += shb[i];
    const float inv = 1.0f / tot;
    for (int i = tid; i < HW; i += 256) p[i] *= inv;
}

// ---------------------------------------------------------------------------
// Launch
// ---------------------------------------------------------------------------
extern "C" void kernel_launch(void* const* d_in, const int* in_sizes, int n_in,
                              void* d_out, int out_size) {
    const float* x     = (const float*)d_in[0];
    const float* gamma = (const float*)d_in[1];
    const float* beta  = (const float*)d_in[2];
    const float* wq    = (const float*)d_in[3];
    const float* bq    = (const float*)d_in[4];
    const float* wk    = (const float*)d_in[5];
    const float* bk    = (const float*)d_in[6];
    const float* wv    = (const float*)d_in[7];
    const float* bv    = (const float*)d_in[8];
    const float* wp    = (const float*)d_in[9];
    const float* bp    = (const float*)d_in[10];
    float* out = (float*)d_out;

    float *xn, *q, *k, *v, *s, *ao;
    cudaGetSymbolAddress((void**)&xn, g_xn);
    cudaGetSymbolAddress((void**)&q,  g_q);
    cudaGetSymbolAddress((void**)&k,  g_k);
    cudaGetSymbolAddress((void**)&v,  g_v);
    cudaGetSymbolAddress((void**)&s,  g_s);
    cudaGetSymbolAddress((void**)&ao, g_ao);

    const long CHW = (long)CH * HW;         // 1048576
    const long SHW = (long)HW * HW;         // 16777216

    // 1) GroupNorm
    gn_kernel<<<BATCH * GROUPS, 256>>>(x, gamma, beta, xn);

    // 2) Q/K/V 1x1 convs: C[c_out, hw] = W[c_out, c_in] @ xn[c_in, hw] + bias
    dim3 gconv(HW / BN, CH / BM, BATCH);
    gemm_kernel<<<gconv, 256>>>(wq, xn, q, bq, nullptr, CH, HW, CH,
                                CH, 1, HW, 1, 0, CHW, CHW, 0, 1.0f);
    gemm_kernel<<<gconv, 256>>>(wk, xn, k, bk, nullptr, CH, HW, CH,
                                CH, 1, HW, 1, 0, CHW, CHW, 0, 1.0f);
    gemm_kernel<<<gconv, 256>>>(wv, xn, v, bv, nullptr, CH, HW, CH,
                                CH, 1, HW, 1, 0, CHW, CHW, 0, 1.0f);

    // 3) S[m, n] = (1/sqrt(C)) * sum_c Q[c, m] K[c, n]
    dim3 gs(HW / BN, HW / BM, BATCH);
    gemm_kernel<<<gs, 256>>>(q, k, s, nullptr, nullptr, HW, HW, CH,
                             1, HW, HW, 1, CHW, CHW, SHW, 0, 0.0625f);

    // 4) softmax rows
    softmax_kernel<<<BATCH * HW, 256>>>(s);

    // 5) AO[c, m] = sum_n V[c, n] P[m, n]   (gemm-M = c, gemm-N = m, gemm-K = n)
    gemm_kernel<<<gconv, 256>>>(v, s, ao, nullptr, nullptr, CH, HW, HW,
                                HW, 1, 1, HW, CHW, SHW, CHW, 0, 1.0f);

    // 6) proj + residual: out[d, m] = Wp[d, c] @ AO[c, m] + bp[d] + x[d, m]
    gemm_kernel<<<gconv, 256>>>(wp, ao, out, bp, x, CH, HW, CH,
                                CH, 1, HW, 1, 0, CHW, CHW, CHW, 1.0f);
}

// round 5
// speedup vs baseline: 3.3934x; 3.3934x over previous
#include <cuda_runtime.h>
#include <cuda_bf16.h>
#include <math.h>
#include <stdint.h>

// Problem constants
#define BATCH 4
#define CH    256
#define HW    4096
#define GROUPS 8
#define CPG   32
#define EPS   1e-5f

// GEMM tiling
#define BM 128
#define BN 128
#define BKT 16            // K per tile (one m16n8k16 step)
#define KP  8             // pair-rows (2 bf16 per uint32) per tile
#define STRIDE 136        // 128 + 8 pad -> conflict-free fragment LDS

// ---------------------------------------------------------------------------
// Scratch (device globals — no allocations allowed)
// ---------------------------------------------------------------------------
__device__ float g_xn [(size_t)BATCH * CH * HW];
__device__ float g_q  [(size_t)BATCH * CH * HW];
__device__ float g_k  [(size_t)BATCH * CH * HW];
__device__ float g_v  [(size_t)BATCH * CH * HW];
__device__ float g_aot[(size_t)BATCH * CH * HW];   // AO transposed: [q][c]
__device__ float g_s  [(size_t)BATCH * HW * HW];   // 268 MB attention probs

// ---------------------------------------------------------------------------
// split-bf16 helpers: a = hi + lo (each bf16), packed 2-per-uint32 along k
// ---------------------------------------------------------------------------
__device__ __forceinline__ void split2(float f0, float f1, uint32_t& hi, uint32_t& lo) {
    __nv_bfloat16 h0 = __float2bfloat16_rn(f0);
    __nv_bfloat16 h1 = __float2bfloat16_rn(f1);
    float r0 = f0 - __bfloat162float(h0);
    float r1 = f1 - __bfloat162float(h1);
    __nv_bfloat16 l0 = __float2bfloat16_rn(r0);
    __nv_bfloat16 l1 = __float2bfloat16_rn(r1);
    hi = ((uint32_t)__bfloat16_as_ushort(h1) << 16) | (uint32_t)__bfloat16_as_ushort(h0);
    lo = ((uint32_t)__bfloat16_as_ushort(l1) << 16) | (uint32_t)__bfloat16_as_ushort(l0);
}

#define MMA16816(d, a, b)                                                     \
    asm volatile("mma.sync.aligned.m16n8k16.row.col.f32.bf16.bf16.f32 "       \
                 "{%0,%1,%2,%3}, {%4,%5,%6,%7}, {%8,%9}, {%0,%1,%2,%3};"      \
                 : "+f"(d[0]), "+f"(d[1]), "+f"(d[2]), "+f"(d[3])             \
                 : "r"(a[0]), "r"(a[1]), "r"(a[2]), "r"(a[3]),                \
                   "r"(b[0]), "r"(b[1]))

// ---------------------------------------------------------------------------
// Tile loaders.
// PATH 0: operand rows run along the m/n dim, k is unit-stride.
//         thread: r = tid/2 (0..127), kh = (tid&1)*8; two float4 along k.
// PATH 1: k rows are strided (stride s_k), m/n is unit-stride.
//         thread: kp = tid/32 (0..7), c = (tid&31)*4; float4 along m/n for
//         k-even and k-odd rows.
// ---------------------------------------------------------------------------
template<int PATH>
__device__ __forceinline__ void ldg_tile(const float* __restrict__ P,
                                         long s_row, long s_k,
                                         int row0, int k0, int tid,
                                         float4& f0, float4& f1) {
    if (PATH == 0) {
        int r = tid >> 1, kh = (tid & 1) << 3;
        const float* p = P + (long)(row0 + r) * s_row + (k0 + kh);
        f0 = *reinterpret_cast<const float4*>(p);
        f1 = *reinterpret_cast<const float4*>(p + 4);
    } else {
        int kp = tid >> 5, c = (tid & 31) << 2;
        const float* p = P + (long)(k0 + 2 * kp) * s_k + (row0 + c);
        f0 = *reinterpret_cast<const float4*>(p);
        f1 = *reinterpret_cast<const float4*>(p + s_k);
    }
}

template<int PATH>
__device__ __forceinline__ void sts_tile(uint32_t (*Sh)[STRIDE], uint32_t (*Sl)[STRIDE],
                                         int tid, float4 f0, float4 f1) {
    if (PATH == 0) {
        int r = tid >> 1, kp0 = (tid & 1) << 2;
        uint32_t h, l;
        split2(f0.x, f0.y, h, l); Sh[kp0 + 0][r] = h; Sl[kp0 + 0][r] = l;
        split2(f0.z, f0.w, h, l); Sh[kp0 + 1][r] = h; Sl[kp0 + 1][r] = l;
        split2(f1.x, f1.y, h, l); Sh[kp0 + 2][r] = h; Sl[kp0 + 2][r] = l;
        split2(f1.z, f1.w, h, l); Sh[kp0 + 3][r] = h; Sl[kp0 + 3][r] = l;
    } else {
        int kp = tid >> 5, c = (tid & 31) << 2;
        uint4 H, L;
        split2(f0.x, f1.x, H.x, L.x);
        split2(f0.y, f1.y, H.y, L.y);
        split2(f0.z, f1.z, H.z, L.z);
        split2(f0.w, f1.w, H.w, L.w);
        *reinterpret_cast<uint4*>(&Sh[kp][c]) = H;
        *reinterpret_cast<uint4*>(&Sl[kp][c]) = L;
    }
}

// ---------------------------------------------------------------------------
// Split-bf16 tensor-core GEMM.
//   C[m,n] = alpha * sum_k A[m*as_m + k*as_k] * B[k*bs_k + n*bs_n]
//            (+ bias[m]) (+ res[m*N+n]),  C row-major leading dim N.
// APATH: 0 -> as_k==1 (k contiguous), 1 -> as_m==1 (m contiguous)
// BPATH: 0 -> bs_k==1 (k contiguous), 1 -> bs_n==1 (n contiguous)
// 256 threads, block tile 128x128x16, double-buffered smem, warp tile 64x32.
// ---------------------------------------------------------------------------
template<int APATH, int BPATH>
__global__ __launch_bounds__(256)
void mma_gemm(const float* __restrict__ A, const float* __restrict__ B,
              float* __restrict__ C,
              const float* __restrict__ bias, const float* __restrict__ res,
              int M, int N, int K,
              long as_m, long as_k, long bs_k, long bs_n,
              long aB, long bB, long cB, long rB, float alpha) {
    __shared__ __align__(16) uint32_t Ah[2][KP][STRIDE];
    __shared__ __align__(16) uint32_t Al[2][KP][STRIDE];
    __shared__ __align__(16) uint32_t Bh[2][KP][STRIDE];
    __shared__ __align__(16) uint32_t Bl[2][KP][STRIDE];

    const int bz = blockIdx.z;
    A += (long)bz * aB;
    B += (long)bz * bB;
    C += (long)bz * cB;
    if (res) res += (long)bz * rB;

    const int tid  = threadIdx.x;
    const int warp = tid >> 5, lane = tid & 31;
    const int wm = warp & 1, wn = warp >> 1;   // 2 warps along M (64 rows), 4 along N (32 cols)
    const int g  = lane >> 2, tg = lane & 3;
    const int m0 = blockIdx.y * BM;
    const int n0 = blockIdx.x * BN;
    const int mbase = wm * 64, nbase = wn * 32;

    float acc[4][4][4] = {};

    const int T = K >> 4;
    float4 fa0, fa1, fb0, fb1;

    // prologue: tile 0
    ldg_tile<APATH>(A, as_m, as_k, m0, 0, tid, fa0, fa1);
    ldg_tile<BPATH == 1 ? 1 : 0>(B, bs_n, bs_k, n0, 0, tid, fb0, fb1);
    sts_tile<APATH>(Ah[0], Al[0], tid, fa0, fa1);
    sts_tile<BPATH == 1 ? 1 : 0>(Bh[0], Bl[0], tid, fb0, fb1);
    __syncthreads();

    for (int t = 0; t < T; t++) {
        const int buf = t & 1;
        if (t + 1 < T) {
            const int k0 = (t + 1) << 4;
            ldg_tile<APATH>(A, as_m, as_k, m0, k0, tid, fa0, fa1);
            ldg_tile<BPATH == 1 ? 1 : 0>(B, bs_n, bs_k, n0, k0, tid, fb0, fb1);
        }

        // fragments
        uint32_t ah[4][4], al[4][4], bh[4][2], bl[4][2];
        #pragma unroll
        for (int mt = 0; mt < 4; mt++) {
            const int mr = mbase + mt * 16 + g;
            ah[mt][0] = Ah[buf][tg][mr];
            ah[mt][1] = Ah[buf][tg][mr + 8];
            ah[mt][2] = Ah[buf][tg + 4][mr];
            ah[mt][3] = Ah[buf][tg + 4][mr + 8];
            al[mt][0] = Al[buf][tg][mr];
            al[mt][1] = Al[buf][tg][mr + 8];
            al[mt][2] = Al[buf][tg + 4][mr];
            al[mt][3] = Al[buf][tg + 4][mr + 8];
        }
        #pragma unroll
        for (int nt = 0; nt < 4; nt++) {
            const int nc = nbase + nt * 8 + g;
            bh[nt][0] = Bh[buf][tg][nc];
            bh[nt][1] = Bh[buf][tg + 4][nc];
            bl[nt][0] = Bl[buf][tg][nc];
            bl[nt][1] = Bl[buf][tg + 4][nc];
        }

        #pragma unroll
        for (int mt = 0; mt < 4; mt++)
            #pragma unroll
            for (int nt = 0; nt < 4; nt++) {
                MMA16816(acc[mt][nt], ah[mt], bh[nt]);   // hi*hi
                MMA16816(acc[mt][nt], ah[mt], bl[nt]);   // hi*lo
                MMA16816(acc[mt][nt], al[mt], bh[nt]);   // lo*hi
            }

        if (t + 1 < T) {
            sts_tile<APATH>(Ah[buf ^ 1], Al[buf ^ 1], tid, fa0, fa1);
            sts_tile<BPATH == 1 ? 1 : 0>(Bh[buf ^ 1], Bl[buf ^ 1], tid, fb0, fb1);
        }
        __syncthreads();
    }

    // epilogue
    #pragma unroll
    for (int mt = 0; mt < 4; mt++) {
        #pragma unroll
        for (int i = 0; i < 2; i++) {
            const int m = m0 + mbase + mt * 16 + g + i * 8;
            const float bv = bias ? bias[m] : 0.f;
            #pragma unroll
            for (int nt = 0; nt < 4; nt++) {
                const int n = n0 + nbase + nt * 8 + tg * 2;
                float v0 = acc[mt][nt][i * 2 + 0] * alpha + bv;
                float v1 = acc[mt][nt][i * 2 + 1] * alpha + bv;
                if (res) {
                    float2 rr = *reinterpret_cast<const float2*>(&res[(long)m * N + n]);
                    v0 += rr.x; v1 += rr.y;
                }
                *reinterpret_cast<float2*>(&C[(long)m * N + n]) = make_float2(v0, v1);
            }
        }
    }
}

// ---------------------------------------------------------------------------
// GroupNorm: one block per (batch, group).
// ---------------------------------------------------------------------------
__global__ void gn_kernel(const float* __restrict__ x,
                          const float* __restrict__ gamma,
                          const float* __restrict__ beta,
                          float* __restrict__ xn) {
    const int bg = blockIdx.x;
    const int b = bg >> 3;
    const int g = bg & 7;
    const size_t base = ((size_t)b * CH + (size_t)g * CPG) * HW;
    const int n = CPG * HW;

    float s = 0.f, ss = 0.f;
    for (int i = threadIdx.x; i < n; i += 256) {
        float v = x[base + i];
        s += v; ss += v * v;
    }
    #pragma unroll
    for (int o = 16; o > 0; o >>= 1) {
        s  += __shfl_down_sync(0xffffffffu, s,  o);
        ss += __shfl_down_sync(0xffffffffu, ss, o);
    }
    __shared__ float sh[18];
    const int warp = threadIdx.x >> 5, lane = threadIdx.x & 31;
    if (lane == 0) { sh[warp] = s; sh[warp + 8] = ss; }
    __syncthreads();
    if (threadIdx.x == 0) {
        float S = 0.f, SS = 0.f;
        #pragma unroll
        for (int i = 0; i < 8; i++) { S += sh[i]; SS += sh[i + 8]; }
        float mean = S / (float)n;
        float var  = SS / (float)n - mean * mean;
        sh[16] = mean;
        sh[17] = rsqrtf(var + EPS);
    }
    __syncthreads();
    const float mean = sh[16], inv = sh[17];
    for (int i = threadIdx.x; i < n; i += 256) {
        int c = g * CPG + (i >> 12);
        xn[base + i] = (x[base + i] - mean) * inv * gamma[c] + beta[c];
    }
}

// ---------------------------------------------------------------------------
// Single-pass row softmax: row of 4096 lives in registers (16 floats/thread).
// ---------------------------------------------------------------------------
__global__ __launch_bounds__(256)
void softmax_kernel(float* __restrict__ S) {
    float* p = S + (size_t)blockIdx.x * HW;
    const int tid = threadIdx.x;
    __shared__ float sh[8];

    float4 r[4];
    #pragma unroll
    for (int i = 0; i < 4; i++)
        r[i] = *reinterpret_cast<const float4*>(p + i * 1024 + tid * 4);

    float m = -INFINITY;
    #pragma unroll
    for (int i = 0; i < 4; i++) {
        m = fmaxf(m, fmaxf(fmaxf(r[i].x, r[i].y), fmaxf(r[i].z, r[i].w)));
    }
    #pragma unroll
    for (int o = 16; o > 0; o >>= 1) m = fmaxf(m, __shfl_xor_sync(0xffffffffu, m, o));
    if ((tid & 31) == 0) sh[tid >> 5] = m;
    __syncthreads();
    float rm = sh[0];
    #pragma unroll
    for (int i = 1; i < 8; i++) rm = fmaxf(rm, sh[i]);
    __syncthreads();

    float sum = 0.f;
    #pragma unroll
    for (int i = 0; i < 4; i++) {
        r[i].x = __expf(r[i].x - rm); sum += r[i].x;
        r[i].y = __expf(r[i].y - rm); sum += r[i].y;
        r[i].z = __expf(r[i].z - rm); sum += r[i].z;
        r[i].w = __expf(r[i].w - rm); sum += r[i].w;
    }
    #pragma unroll
    for (int o = 16; o > 0; o >>= 1) sum += __shfl_xor_sync(0xffffffffu, sum, o);
    if ((tid & 31) == 0) sh[tid >> 5] = sum;
    __syncthreads();
    float tot = 0.f;
    #pragma unroll
    for (int i = 0; i < 8; i++) tot += sh[i];
    const float inv = 1.0f / tot;

    #pragma unroll
    for (int i = 0; i < 4; i++) {
        r[i].x *= inv; r[i].y *= inv; r[i].z *= inv; r[i].w *= inv;
        *reinterpret_cast<float4*>(p + i * 1024 + tid * 4) = r[i];
    }
}

// ---------------------------------------------------------------------------
// Launch
// ---------------------------------------------------------------------------
extern "C" void kernel_launch(void* const* d_in, const int* in_sizes, int n_in,
                              void* d_out, int out_size) {
    const float* x     = (const float*)d_in[0];
    const float* gamma = (const float*)d_in[1];
    const float* beta  = (const float*)d_in[2];
    const float* wq    = (const float*)d_in[3];
    const float* bq    = (const float*)d_in[4];
    const float* wk    = (const float*)d_in[5];
    const float* bk    = (const float*)d_in[6];
    const float* wv    = (const float*)d_in[7];
    const float* bv    = (const float*)d_in[8];
    const float* wp    = (const float*)d_in[9];
    const float* bp    = (const float*)d_in[10];
    float* out = (float*)d_out;

    float *xn, *q, *k, *v, *s, *aot;
    cudaGetSymbolAddress((void**)&xn,  g_xn);
    cudaGetSymbolAddress((void**)&q,   g_q);
    cudaGetSymbolAddress((void**)&k,   g_k);
    cudaGetSymbolAddress((void**)&v,   g_v);
    cudaGetSymbolAddress((void**)&s,   g_s);
    cudaGetSymbolAddress((void**)&aot, g_aot);

    const long CHW = (long)CH * HW;
    const long SHW = (long)HW * HW;

    // 1) GroupNorm
    gn_kernel<<<BATCH * GROUPS, 256>>>(x, gamma, beta, xn);

    // 2) Q/K/V: C[cout, hw] = W[cout, cin] @ xn[cin, hw] + bias
    //    A = W: k contiguous (APATH 0). B = xn: n contiguous (BPATH 1).
    dim3 gconv(HW / BN, CH / BM, BATCH);
    mma_gemm<0, 1><<<gconv, 256>>>(wq, xn, q, bq, nullptr, CH, HW, CH,
                                   CH, 1, HW, 1, 0, CHW, CHW, 0, 1.0f);
    mma_gemm<0, 1><<<gconv, 256>>>(wk, xn, k, bk, nullptr, CH, HW, CH,
                                   CH, 1, HW, 1, 0, CHW, CHW, 0, 1.0f);
    mma_gemm<0, 1><<<gconv, 256>>>(wv, xn, v, bv, nullptr, CH, HW, CH,
                                   CH, 1, HW, 1, 0, CHW, CHW, 0, 1.0f);

    // 3) S[q, kv] = (1/16) * sum_c Q[c, q] K[c, kv]
    //    A = Q^T: m contiguous (APATH 1). B = K: n contiguous (BPATH 1).
    dim3 gs(HW / BN, HW / BM, BATCH);
    mma_gemm<1, 1><<<gs, 256>>>(q, k, s, nullptr, nullptr, HW, HW, CH,
                                1, HW, HW, 1, CHW, CHW, SHW, 0, 0.0625f);

    // 4) softmax rows (in place)
    softmax_kernel<<<BATCH * HW, 256>>>(s);

    // 5) AOt[q, c] = sum_kv P[q, kv] V[c, kv]
    //    A = P: k contiguous (APATH 0). B = V^T: k contiguous (BPATH 0).
    dim3 gpv(CH / BN, HW / BM, BATCH);
    mma_gemm<0, 0><<<gpv, 256>>>(s, v, aot, nullptr, nullptr, HW, CH, HW,
                                 HW, 1, 1, HW, SHW, CHW, CHW, 0, 1.0f);

    // 6) out[cout, q] = Wp[cout, c] @ AOt^T[c, q] + bp + x
    //    A = Wp: k contiguous (APATH 0). B = AOt: bs_k=1, bs_n=CH (BPATH 0).
    dim3 gproj(HW / BN, CH / BM, BATCH);
    mma_gemm<0, 0><<<gproj, 256>>>(wp, aot, out, bp, x, CH, HW, CH,
                                   CH, 1, 1, CH, 0, CHW, CHW, CHW, 1.0f);
}

// round 11
// speedup vs baseline: 3.8632x; 1.1384x over previous
#include <cuda_runtime.h>
#include <cuda_bf16.h>
#include <math.h>
#include <stdint.h>

// Problem constants
#define BATCH 4
#define CH    256
#define HW    4096
#define GROUPS 8
#define CPG   32
#define EPS   1e-5f

// GEMM tiling
#define BM 128
#define BN 128
#define KP  8             // pair-rows (2 bf16 per uint32) per tile
#define STRIDE 136        // 128 + 8 pad -> conflict-free fragment LDS

// ---------------------------------------------------------------------------
// Scratch (device globals — no allocations allowed)
// ---------------------------------------------------------------------------
__device__ float g_xn [(size_t)BATCH * CH * HW];
__device__ float g_q  [(size_t)BATCH * CH * HW];
__device__ float g_k  [(size_t)BATCH * CH * HW];
__device__ float g_v  [(size_t)BATCH * CH * HW];
__device__ float g_aot[(size_t)BATCH * CH * HW];   // AO transposed: [q][c]
__device__ float g_s  [(size_t)BATCH * HW * HW];   // 268 MB attention probs

// ---------------------------------------------------------------------------
// split-bf16 helpers: a = hi + lo (each bf16), packed 2-per-uint32 along k
// ---------------------------------------------------------------------------
__device__ __forceinline__ void split2(float f0, float f1, uint32_t& hi, uint32_t& lo) {
    __nv_bfloat16 h0 = __float2bfloat16_rn(f0);
    __nv_bfloat16 h1 = __float2bfloat16_rn(f1);
    float r0 = f0 - __bfloat162float(h0);
    float r1 = f1 - __bfloat162float(h1);
    __nv_bfloat16 l0 = __float2bfloat16_rn(r0);
    __nv_bfloat16 l1 = __float2bfloat16_rn(r1);
    hi = ((uint32_t)__bfloat16_as_ushort(h1) << 16) | (uint32_t)__bfloat16_as_ushort(h0);
    lo = ((uint32_t)__bfloat16_as_ushort(l1) << 16) | (uint32_t)__bfloat16_as_ushort(l0);
}

#define MMA16816(d, a, b)                                                     \
    asm volatile("mma.sync.aligned.m16n8k16.row.col.f32.bf16.bf16.f32 "       \
                 "{%0,%1,%2,%3}, {%4,%5,%6,%7}, {%8,%9}, {%0,%1,%2,%3};"      \
                 : "+f"(d[0]), "+f"(d[1]), "+f"(d[2]), "+f"(d[3])             \
                 : "r"(a[0]), "r"(a[1]), "r"(a[2]), "r"(a[3]),                \
                   "r"(b[0]), "r"(b[1]))

// ---------------------------------------------------------------------------
// Tile loaders (verified correct in round 5's passing run).
// PATH 0: k unit-stride. PATH 1: m/n unit-stride, k strided.
// ---------------------------------------------------------------------------
template<int PATH>
__device__ __forceinline__ void ldg_tile(const float* __restrict__ P,
                                         long s_row, long s_k,
                                         int row0, int k0, int tid,
                                         float4& f0, float4& f1) {
    if (PATH == 0) {
        int r = tid >> 1, kh = (tid & 1) << 3;
        const float* p = P + (long)(row0 + r) * s_row + (k0 + kh);
        f0 = *reinterpret_cast<const float4*>(p);
        f1 = *reinterpret_cast<const float4*>(p + 4);
    } else {
        int kp = tid >> 5, c = (tid & 31) << 2;
        const float* p = P + (long)(k0 + 2 * kp) * s_k + (row0 + c);
        f0 = *reinterpret_cast<const float4*>(p);
        f1 = *reinterpret_cast<const float4*>(p + s_k);
    }
}

template<int PATH>
__device__ __forceinline__ void sts_tile(uint32_t (*Sh)[STRIDE], uint32_t (*Sl)[STRIDE],
                                         int tid, float4 f0, float4 f1) {
    if (PATH == 0) {
        int r = tid >> 1, kp0 = (tid & 1) << 2;
        uint32_t h, l;
        split2(f0.x, f0.y, h, l); Sh[kp0 + 0][r] = h; Sl[kp0 + 0][r] = l;
        split2(f0.z, f0.w, h, l); Sh[kp0 + 1][r] = h; Sl[kp0 + 1][r] = l;
        split2(f1.x, f1.y, h, l); Sh[kp0 + 2][r] = h; Sl[kp0 + 2][r] = l;
        split2(f1.z, f1.w, h, l); Sh[kp0 + 3][r] = h; Sl[kp0 + 3][r] = l;
    } else {
        int kp = tid >> 5, c = (tid & 31) << 2;
        uint4 H, L;
        split2(f0.x, f1.x, H.x, L.x);
        split2(f0.y, f1.y, H.y, L.y);
        split2(f0.z, f1.z, H.z, L.z);
        split2(f0.w, f1.w, H.w, L.w);
        *reinterpret_cast<uint4*>(&Sh[kp][c]) = H;
        *reinterpret_cast<uint4*>(&Sl[kp][c]) = L;
    }
}

// ---------------------------------------------------------------------------
// Split-bf16 tensor-core GEMM (2 CTAs/SM, reduced register peak).
//   C[m,n] = alpha * sum_k A[.] * B[.] (+ bias[m]) (+ res[m*N+n])
// ---------------------------------------------------------------------------
template<int APATH, int BPATH>
__global__ __launch_bounds__(256, 2)
void mma_gemm(const float* __restrict__ A, const float* __restrict__ B,
              float* __restrict__ C,
              const float* __restrict__ bias, const float* __restrict__ res,
              int M, int N, int K,
              long as_m, long as_k, long bs_k, long bs_n,
              long aB, long bB, long cB, long rB, float alpha) {
    __shared__ __align__(16) uint32_t Ah[2][KP][STRIDE];
    __shared__ __align__(16) uint32_t Al[2][KP][STRIDE];
    __shared__ __align__(16) uint32_t Bh[2][KP][STRIDE];
    __shared__ __align__(16) uint32_t Bl[2][KP][STRIDE];

    const int bz = blockIdx.z;
    A += (long)bz * aB;
    B += (long)bz * bB;
    C += (long)bz * cB;
    if (res) res += (long)bz * rB;

    const int tid  = threadIdx.x;
    const int warp = tid >> 5, lane = tid & 31;
    const int wm = warp & 1, wn = warp >> 1;   // 2 warps along M (64 rows), 4 along N (32 cols)
    const int g  = lane >> 2, tg = lane & 3;
    const int m0 = blockIdx.y * BM;
    const int n0 = blockIdx.x * BN;
    const int mbase = wm * 64, nbase = wn * 32;

    float acc[4][4][4] = {};

    const int T = K >> 4;
    float4 fa0, fa1, fb0, fb1;

    // prologue: tile 0
    ldg_tile<APATH>(A, as_m, as_k, m0, 0, tid, fa0, fa1);
    ldg_tile<BPATH == 1 ? 1 : 0>(B, bs_n, bs_k, n0, 0, tid, fb0, fb1);
    sts_tile<APATH>(Ah[0], Al[0], tid, fa0, fa1);
    sts_tile<BPATH == 1 ? 1 : 0>(Bh[0], Bl[0], tid, fb0, fb1);
    __syncthreads();

    for (int t = 0; t < T; t++) {
        const int buf = t & 1;
        if (t + 1 < T) {
            const int k0 = (t + 1) << 4;
            ldg_tile<APATH>(A, as_m, as_k, m0, k0, tid, fa0, fa1);
            ldg_tile<BPATH == 1 ? 1 : 0>(B, bs_n, bs_k, n0, k0, tid, fb0, fb1);
        }

        // B fragments once (16 regs live)
        uint32_t bh[4][2], bl[4][2];
        #pragma unroll
        for (int nt = 0; nt < 4; nt++) {
            const int nc = nbase + nt * 8 + g;
            bh[nt][0] = Bh[buf][tg][nc];
            bh[nt][1] = Bh[buf][tg + 4][nc];
            bl[nt][0] = Bl[buf][tg][nc];
            bl[nt][1] = Bl[buf][tg + 4][nc];
        }

        // per-mt: load that row's A fragments (8 regs), issue its 12 MMAs
        #pragma unroll
        for (int mt = 0; mt < 4; mt++) {
            uint32_t ah[4], al[4];
            const int mr = mbase + mt * 16 + g;
            ah[0] = Ah[buf][tg][mr];
            ah[1] = Ah[buf][tg][mr + 8];
            ah[2] = Ah[buf][tg + 4][mr];
            ah[3] = Ah[buf][tg + 4][mr + 8];
            al[0] = Al[buf][tg][mr];
            al[1] = Al[buf][tg][mr + 8];
            al[2] = Al[buf][tg + 4][mr];
            al[3] = Al[buf][tg + 4][mr + 8];
            #pragma unroll
            for (int nt = 0; nt < 4; nt++) {
                MMA16816(acc[mt][nt], ah, bh[nt]);   // hi*hi
                MMA16816(acc[mt][nt], ah, bl[nt]);   // hi*lo
                MMA16816(acc[mt][nt], al, bh[nt]);   // lo*hi
            }
        }

        if (t + 1 < T) {
            sts_tile<APATH>(Ah[buf ^ 1], Al[buf ^ 1], tid, fa0, fa1);
            sts_tile<BPATH == 1 ? 1 : 0>(Bh[buf ^ 1], Bl[buf ^ 1], tid, fb0, fb1);
        }
        __syncthreads();
    }

    // epilogue
    #pragma unroll
    for (int mt = 0; mt < 4; mt++) {
        #pragma unroll
        for (int i = 0; i < 2; i++) {
            const int m = m0 + mbase + mt * 16 + g + i * 8;
            const float bv = bias ? bias[m] : 0.f;
            #pragma unroll
            for (int nt = 0; nt < 4; nt++) {
                const int n = n0 + nbase + nt * 8 + tg * 2;
                float v0 = acc[mt][nt][i * 2 + 0] * alpha + bv;
                float v1 = acc[mt][nt][i * 2 + 1] * alpha + bv;
                if (res) {
                    float2 rr = *reinterpret_cast<const float2*>(&res[(long)m * N + n]);
                    v0 += rr.x; v1 += rr.y;
                }
                *reinterpret_cast<float2*>(&C[(long)m * N + n]) = make_float2(v0, v1);
            }
        }
    }
}

// ---------------------------------------------------------------------------
// GroupNorm: one block per (batch, group).
// ---------------------------------------------------------------------------
__global__ void gn_kernel(const float* __restrict__ x,
                          const float* __restrict__ gamma,
                          const float* __restrict__ beta,
                          float* __restrict__ xn) {
    const int bg = blockIdx.x;
    const int b = bg >> 3;
    const int g = bg & 7;
    const size_t base = ((size_t)b * CH + (size_t)g * CPG) * HW;
    const int n = CPG * HW;

    float s = 0.f, ss = 0.f;
    for (int i = threadIdx.x; i < n; i += 256) {
        float v = x[base + i];
        s += v; ss += v * v;
    }
    #pragma unroll
    for (int o = 16; o > 0; o >>= 1) {
        s  += __shfl_down_sync(0xffffffffu, s,  o);
        ss += __shfl_down_sync(0xffffffffu, ss, o);
    }
    __shared__ float sh[18];
    const int warp = threadIdx.x >> 5, lane = threadIdx.x & 31;
    if (lane == 0) { sh[warp] = s; sh[warp + 8] = ss; }
    __syncthreads();
    if (threadIdx.x == 0) {
        float S = 0.f, SS = 0.f;
        #pragma unroll
        for (int i = 0; i < 8; i++) { S += sh[i]; SS += sh[i + 8]; }
        float mean = S / (float)n;
        float var  = SS / (float)n - mean * mean;
        sh[16] = mean;
        sh[17] = rsqrtf(var + EPS);
    }
    __syncthreads();
    const float mean = sh[16], inv = sh[17];
    for (int i = threadIdx.x; i < n; i += 256) {
        int c = g * CPG + (i >> 12);
        xn[base + i] = (x[base + i] - mean) * inv * gamma[c] + beta[c];
    }
}

// ---------------------------------------------------------------------------
// Single-pass row softmax: row of 4096 lives in registers (16 floats/thread).
// ---------------------------------------------------------------------------
__global__ __launch_bounds__(256)
void softmax_kernel(float* __restrict__ S) {
    float* p = S + (size_t)blockIdx.x * HW;
    const int tid = threadIdx.x;
    __shared__ float sh[8];

    float4 r[4];
    #pragma unroll
    for (int i = 0; i < 4; i++)
        r[i] = *reinterpret_cast<const float4*>(p + i * 1024 + tid * 4);

    float m = -INFINITY;
    #pragma unroll
    for (int i = 0; i < 4; i++) {
        m = fmaxf(m, fmaxf(fmaxf(r[i].x, r[i].y), fmaxf(r[i].z, r[i].w)));
    }
    #pragma unroll
    for (int o = 16; o > 0; o >>= 1) m = fmaxf(m, __shfl_xor_sync(0xffffffffu, m, o));
    if ((tid & 31) == 0) sh[tid >> 5] = m;
    __syncthreads();
    float rm = sh[0];
    #pragma unroll
    for (int i = 1; i < 8; i++) rm = fmaxf(rm, sh[i]);
    __syncthreads();

    float sum = 0.f;
    #pragma unroll
    for (int i = 0; i < 4; i++) {
        r[i].x = __expf(r[i].x - rm); sum += r[i].x;
        r[i].y = __expf(r[i].y - rm); sum += r[i].y;
        r[i].z = __expf(r[i].z - rm); sum += r[i].z;
        r[i].w = __expf(r[i].w - rm); sum += r[i].w;
    }
    #pragma unroll
    for (int o = 16; o > 0; o >>= 1) sum += __shfl_xor_sync(0xffffffffu, sum, o);
    if ((tid & 31) == 0) sh[tid >> 5] = sum;
    __syncthreads();
    float tot = 0.f;
    #pragma unroll
    for (int i = 0; i < 8; i++) tot += sh[i];
    const float inv = 1.0f / tot;

    #pragma unroll
    for (int i = 0; i < 4; i++) {
        r[i].x *= inv; r[i].y *= inv; r[i].z *= inv; r[i].w *= inv;
        *reinterpret_cast<float4*>(p + i * 1024 + tid * 4) = r[i];
    }
}

// ---------------------------------------------------------------------------
// Launch
// ---------------------------------------------------------------------------
extern "C" void kernel_launch(void* const* d_in, const int* in_sizes, int n_in,
                              void* d_out, int out_size) {
    const float* x     = (const float*)d_in[0];
    const float* gamma = (const float*)d_in[1];
    const float* beta  = (const float*)d_in[2];
    const float* wq    = (const float*)d_in[3];
    const float* bq    = (const float*)d_in[4];
    const float* wk    = (const float*)d_in[5];
    const float* bk    = (const float*)d_in[6];
    const float* wv    = (const float*)d_in[7];
    const float* bv    = (const float*)d_in[8];
    const float* wp    = (const float*)d_in[9];
    const float* bp    = (const float*)d_in[10];
    float* out = (float*)d_out;

    float *xn, *q, *k, *v, *s, *aot;
    cudaGetSymbolAddress((void**)&xn,  g_xn);
    cudaGetSymbolAddress((void**)&q,   g_q);
    cudaGetSymbolAddress((void**)&k,   g_k);
    cudaGetSymbolAddress((void**)&v,   g_v);
    cudaGetSymbolAddress((void**)&s,   g_s);
    cudaGetSymbolAddress((void**)&aot, g_aot);

    const long CHW = (long)CH * HW;
    const long SHW = (long)HW * HW;

    // 1) GroupNorm
    gn_kernel<<<BATCH * GROUPS, 256>>>(x, gamma, beta, xn);

    // 2) Q/K/V: C[cout, hw] = W[cout, cin] @ xn[cin, hw] + bias
    dim3 gconv(HW / BN, CH / BM, BATCH);
    mma_gemm<0, 1><<<gconv, 256>>>(wq, xn, q, bq, nullptr, CH, HW, CH,
                                   CH, 1, HW, 1, 0, CHW, CHW, 0, 1.0f);
    mma_gemm<0, 1><<<gconv, 256>>>(wk, xn, k, bk, nullptr, CH, HW, CH,
                                   CH, 1, HW, 1, 0, CHW, CHW, 0, 1.0f);
    mma_gemm<0, 1><<<gconv, 256>>>(wv, xn, v, bv, nullptr, CH, HW, CH,
                                   CH, 1, HW, 1, 0, CHW, CHW, 0, 1.0f);

    // 3) S[q, kv] = (1/16) * sum_c Q[c, q] K[c, kv]
    dim3 gs(HW / BN, HW / BM, BATCH);
    mma_gemm<1, 1><<<gs, 256>>>(q, k, s, nullptr, nullptr, HW, HW, CH,
                                1, HW, HW, 1, CHW, CHW, SHW, 0, 0.0625f);

    // 4) softmax rows (in place)
    softmax_kernel<<<BATCH * HW, 256>>>(s);

    // 5) AOt[q, c] = sum_kv P[q, kv] V[c, kv]
    dim3 gpv(CH / BN, HW / BM, BATCH);
    mma_gemm<0, 0><<<gpv, 256>>>(s, v, aot, nullptr, nullptr, HW, CH, HW,
                                 HW, 1, 1, HW, SHW, CHW, CHW, 0, 1.0f);

    // 6) out[cout, q] = Wp[cout, c] @ AOt^T[c, q] + bp + x
    dim3 gproj(HW / BN, CH / BM, BATCH);
    mma_gemm<0, 0><<<gproj, 256>>>(wp, aot, out, bp, x, CH, HW, CH,
                                   CH, 1, 1, CH, 0, CHW, CHW, CHW, 1.0f);
}

// round 16
// speedup vs baseline: 4.4932x; 1.1631x over previous
#include <cuda_runtime.h>
#include <cuda_bf16.h>
#include <math.h>
#include <stdint.h>

// Problem constants
#define BATCH 4
#define CH    256
#define HW    4096
#define GROUPS 8
#define CPG   32
#define EPS   1e-5f

// GEMM tiling: block 128x128x16, warp 64x32, all operands k-contiguous.
#define BM 128
#define BN 128
#define LDW 12    // uint32 words per smem row: 8 data (16 bf16) + 4 pad -> 48B rows, LDSM conflict-free

// ---------------------------------------------------------------------------
// Scratch (device globals — no allocations allowed)
// ---------------------------------------------------------------------------
__device__ float g_xnt[(size_t)BATCH * CH * HW];   // xnT: [hw][c]
__device__ float g_qt [(size_t)BATCH * CH * HW];   // Qt:  [hw][c]
__device__ float g_kt [(size_t)BATCH * CH * HW];   // Kt:  [hw][c]
__device__ float g_v  [(size_t)BATCH * CH * HW];   // V:   [c][hw]
__device__ float g_aot[(size_t)BATCH * CH * HW];   // AOt: [q][c]
__device__ float g_s  [(size_t)BATCH * HW * HW];   // S/P: [q][kv]

// ---------------------------------------------------------------------------
// split-bf16: a = hi + lo, packed 2-per-uint32 along k
// ---------------------------------------------------------------------------
__device__ __forceinline__ void split2(float f0, float f1, uint32_t& hi, uint32_t& lo) {
    __nv_bfloat16 h0 = __float2bfloat16_rn(f0);
    __nv_bfloat16 h1 = __float2bfloat16_rn(f1);
    float r0 = f0 - __bfloat162float(h0);
    float r1 = f1 - __bfloat162float(h1);
    __nv_bfloat16 l0 = __float2bfloat16_rn(r0);
    __nv_bfloat16 l1 = __float2bfloat16_rn(r1);
    hi = ((uint32_t)__bfloat16_as_ushort(h1) << 16) | (uint32_t)__bfloat16_as_ushort(h0);
    lo = ((uint32_t)__bfloat16_as_ushort(l1) << 16) | (uint32_t)__bfloat16_as_ushort(l0);
}

#define MMA16816(d, a, b)                                                     \
    asm volatile("mma.sync.aligned.m16n8k16.row.col.f32.bf16.bf16.f32 "       \
                 "{%0,%1,%2,%3}, {%4,%5,%6,%7}, {%8,%9}, {%0,%1,%2,%3};"      \
                 : "+f"(d[0]), "+f"(d[1]), "+f"(d[2]), "+f"(d[3])             \
                 : "r"(a[0]), "r"(a[1]), "r"(a[2]), "r"(a[3]),                \
                   "r"(b[0]), "r"(b[1]))

#define LDSM4(r0, r1, r2, r3, addr)                                           \
    asm volatile("ldmatrix.sync.aligned.m8n8.x4.shared.b16 {%0,%1,%2,%3}, [%4];" \
                 : "=r"(r0), "=r"(r1), "=r"(r2), "=r"(r3) : "r"(addr))

// ---------------------------------------------------------------------------
// Unified split-bf16 tensor-core GEMM, all operands k-contiguous:
//   C[m,n] = alpha * sum_k A[m*lda + k] * B[n*ldb + k]
//            (+ bias[m] or bias[n]) (+ res[m*N+n]),  C row-major ld N.
// BIAS_N: 0 -> bias indexed by m, 1 -> bias indexed by n. bias may be null.
// ---------------------------------------------------------------------------
template<int BIAS_N>
__global__ __launch_bounds__(256, 2)
void mma_gemm(const float* __restrict__ A, const float* __restrict__ B,
              float* __restrict__ C,
              const float* __restrict__ bias, const float* __restrict__ res,
              int M, int N, int K, long lda, long ldb,
              long aB, long bB, long cB, long rB, float alpha) {
    // [2 buffers][128 rows][12 words]; 4 arrays * 12 KB = 48 KB static smem
    __shared__ __align__(16) uint32_t Ah[2][BM][LDW];
    __shared__ __align__(16) uint32_t Al[2][BM][LDW];
    __shared__ __align__(16) uint32_t Bh[2][BN][LDW];
    __shared__ __align__(16) uint32_t Bl[2][BN][LDW];

    const int bz = blockIdx.z;
    A += (long)bz * aB;
    B += (long)bz * bB;
    C += (long)bz * cB;
    if (res) res += (long)bz * rB;

    const int tid  = threadIdx.x;
    const int warp = tid >> 5, lane = tid & 31;
    const int wm = warp & 1, wn = warp >> 1;   // 2 warps on M (64 rows), 4 on N (32 cols)
    const int g  = lane >> 2, tg = lane & 3;
    const int m0 = blockIdx.y * BM;
    const int n0 = blockIdx.x * BN;
    const int mbase = wm * 64, nbase = wn * 32;

    // LDSM lane address offsets (bytes), computed once.
    const int sub = lane >> 3, lr = lane & 7;
    const uint32_t a_base = (uint32_t)__cvta_generic_to_shared(&Ah[0][0][0]);
    const uint32_t al_base = (uint32_t)__cvta_generic_to_shared(&Al[0][0][0]);
    const uint32_t b_base = (uint32_t)__cvta_generic_to_shared(&Bh[0][0][0]);
    const uint32_t bl_base = (uint32_t)__cvta_generic_to_shared(&Bl[0][0][0]);
    // A: matrices (m0-7,k0-7),(m8-15,k0-7),(m0-7,k8-15),(m8-15,k8-15)
    const uint32_t a_off = (uint32_t)(((mbase + (sub & 1) * 8 + lr) * LDW + 4 * (sub >> 1)) * 4);
    // B: matrices (n0-7,k0-7),(n0-7,k8-15),(n8-15,k0-7),(n8-15,k8-15)
    const uint32_t b_off = (uint32_t)(((nbase + (sub >> 1) * 8 + lr) * LDW + 4 * (sub & 1)) * 4);
    const uint32_t BUFB = BM * LDW * 4;   // 6144 bytes per buffer

    float acc[4][4][4] = {};
    const int T = K >> 4;

    // per-thread ldg/sts mapping: row r (0..127), k-half h (0..1)
    const int r = tid >> 1, h = tid & 1;
    float4 fa0, fa1, fb0, fb1;

    // prologue: tile 0
    {
        const float* pa = A + (long)(m0 + r) * lda + h * 8;
        const float* pb = B + (long)(n0 + r) * ldb + h * 8;
        fa0 = *reinterpret_cast<const float4*>(pa);
        fa1 = *reinterpret_cast<const float4*>(pa + 4);
        fb0 = *reinterpret_cast<const float4*>(pb);
        fb1 = *reinterpret_cast<const float4*>(pb + 4);
        uint4 H, L;
        split2(fa0.x, fa0.y, H.x, L.x); split2(fa0.z, fa0.w, H.y, L.y);
        split2(fa1.x, fa1.y, H.z, L.z); split2(fa1.z, fa1.w, H.w, L.w);
        *reinterpret_cast<uint4*>(&Ah[0][r][4 * h]) = H;
        *reinterpret_cast<uint4*>(&Al[0][r][4 * h]) = L;
        split2(fb0.x, fb0.y, H.x, L.x); split2(fb0.z, fb0.w, H.y, L.y);
        split2(fb1.x, fb1.y, H.z, L.z); split2(fb1.z, fb1.w, H.w, L.w);
        *reinterpret_cast<uint4*>(&Bh[0][r][4 * h]) = H;
        *reinterpret_cast<uint4*>(&Bl[0][r][4 * h]) = L;
    }
    __syncthreads();

    for (int t = 0; t < T; t++) {
        const int buf = t & 1;
        const uint32_t bo = buf ? BUFB : 0;
        if (t + 1 < T) {
            const int k0 = (t + 1) << 4;
            const float* pa = A + (long)(m0 + r) * lda + k0 + h * 8;
            const float* pb = B + (long)(n0 + r) * ldb + k0 + h * 8;
            fa0 = *reinterpret_cast<const float4*>(pa);
            fa1 = *reinterpret_cast<const float4*>(pa + 4);
            fb0 = *reinterpret_cast<const float4*>(pb);
            fb1 = *reinterpret_cast<const float4*>(pb + 4);
        }

        // B fragments: 4 LDSM.x4 total (hi/lo x 2 n-halves)
        uint32_t bh[4][2], bl[4][2];
        LDSM4(bh[0][0], bh[0][1], bh[1][0], bh[1][1], b_base + bo + b_off);
        LDSM4(bh[2][0], bh[2][1], bh[3][0], bh[3][1], b_base + bo + b_off + 16 * LDW * 4);
        LDSM4(bl[0][0], bl[0][1], bl[1][0], bl[1][1], bl_base + bo + b_off);
        LDSM4(bl[2][0], bl[2][1], bl[3][0], bl[3][1], bl_base + bo + b_off + 16 * LDW * 4);

        #pragma unroll
        for (int mt = 0; mt < 4; mt++) {
            uint32_t ah[4], al4[4];
            const uint32_t mo = bo + a_off + mt * 16 * LDW * 4;
            LDSM4(ah[0], ah[1], ah[2], ah[3], a_base + mo);
            LDSM4(al4[0], al4[1], al4[2], al4[3], al_base + mo);
            #pragma unroll
            for (int nt = 0; nt < 4; nt++) {
                MMA16816(acc[mt][nt], ah, bh[nt]);    // hi*hi
                MMA16816(acc[mt][nt], ah, bl[nt]);    // hi*lo
                MMA16816(acc[mt][nt], al4, bh[nt]);   // lo*hi
            }
        }

        if (t + 1 < T) {
            const int nb = buf ^ 1;
            uint4 H, L;
            split2(fa0.x, fa0.y, H.x, L.x); split2(fa0.z, fa0.w, H.y, L.y);
            split2(fa1.x, fa1.y, H.z, L.z); split2(fa1.z, fa1.w, H.w, L.w);
            *reinterpret_cast<uint4*>(&Ah[nb][r][4 * h]) = H;
            *reinterpret_cast<uint4*>(&Al[nb][r][4 * h]) = L;
            split2(fb0.x, fb0.y, H.x, L.x); split2(fb0.z, fb0.w, H.y, L.y);
            split2(fb1.x, fb1.y, H.z, L.z); split2(fb1.z, fb1.w, H.w, L.w);
            *reinterpret_cast<uint4*>(&Bh[nb][r][4 * h]) = H;
            *reinterpret_cast<uint4*>(&Bl[nb][r][4 * h]) = L;
        }
        __syncthreads();
    }

    // epilogue
    #pragma unroll
    for (int mt = 0; mt < 4; mt++) {
        #pragma unroll
        for (int i = 0; i < 2; i++) {
            const int m = m0 + mbase + mt * 16 + g + i * 8;
            const float bvm = (!BIAS_N && bias) ? bias[m] : 0.f;
            #pragma unroll
            for (int nt = 0; nt < 4; nt++) {
                const int n = n0 + nbase + nt * 8 + tg * 2;
                float v0 = acc[mt][nt][i * 2 + 0] * alpha + bvm;
                float v1 = acc[mt][nt][i * 2 + 1] * alpha + bvm;
                if (BIAS_N && bias) { v0 += bias[n]; v1 += bias[n + 1]; }
                if (res) {
                    float2 rr = *reinterpret_cast<const float2*>(&res[(long)m * N + n]);
                    v0 += rr.x; v1 += rr.y;
                }
                *reinterpret_cast<float2*>(&C[(long)m * N + n]) = make_float2(v0, v1);
            }
        }
    }
}

// ---------------------------------------------------------------------------
// GroupNorm + transpose: reads x[b][c][hw], writes xnT[b][hw][c].
// One block per (batch, group); warp-tiled 32x32 smem transpose.
// ---------------------------------------------------------------------------
__global__ void gn_t_kernel(const float* __restrict__ x,
                            const float* __restrict__ gamma,
                            const float* __restrict__ beta,
                            float* __restrict__ xnT) {
    const int bg = blockIdx.x;
    const int b = bg >> 3;
    const int g = bg & 7;
    const size_t base = ((size_t)b * CH + (size_t)g * CPG) * HW;
    const int n = CPG * HW;

    float s = 0.f, ss = 0.f;
    for (int i = threadIdx.x; i < n; i += 256) {
        float v = x[base + i];
        s += v; ss += v * v;
    }
    #pragma unroll
    for (int o = 16; o > 0; o >>= 1) {
        s  += __shfl_down_sync(0xffffffffu, s,  o);
        ss += __shfl_down_sync(0xffffffffu, ss, o);
    }
    __shared__ float sh[18];
    __shared__ float tile[8][32][33];
    const int warp = threadIdx.x >> 5, lane = threadIdx.x & 31;
    if (lane == 0) { sh[warp] = s; sh[warp + 8] = ss; }
    __syncthreads();
    if (threadIdx.x == 0) {
        float S = 0.f, SS = 0.f;
        #pragma unroll
        for (int i = 0; i < 8; i++) { S += sh[i]; SS += sh[i + 8]; }
        float mean = S / (float)n;
        float var  = SS / (float)n - mean * mean;
        sh[16] = mean;
        sh[17] = rsqrtf(var + EPS);
    }
    __syncthreads();
    const float mean = sh[16], inv = sh[17];

    // transpose-normalize: each warp handles 32-hw-wide tiles
    const size_t outb = (size_t)b * CH * HW;
    for (int hw0 = warp * 32; hw0 < HW; hw0 += 8 * 32) {
        #pragma unroll
        for (int c = 0; c < CPG; c++) {
            float v = x[base + (size_t)c * HW + hw0 + lane];
            tile[warp][c][lane] = (v - mean) * inv * gamma[g * CPG + c] + beta[g * CPG + c];
        }
        __syncwarp();
        #pragma unroll
        for (int i = 0; i < 32; i++) {
            xnT[outb + (size_t)(hw0 + i) * CH + g * CPG + lane] = tile[warp][lane][i];
        }
        __syncwarp();
    }
}

// ---------------------------------------------------------------------------
// Single-pass row softmax (rows of 4096 in registers)
// ---------------------------------------------------------------------------
__global__ __launch_bounds__(256)
void softmax_kernel(float* __restrict__ S) {
    float* p = S + (size_t)blockIdx.x * HW;
    const int tid = threadIdx.x;
    __shared__ float sh[8];

    float4 r[4];
    #pragma unroll
    for (int i = 0; i < 4; i++)
        r[i] = *reinterpret_cast<const float4*>(p + i * 1024 + tid * 4);

    float m = -INFINITY;
    #pragma unroll
    for (int i = 0; i < 4; i++)
        m = fmaxf(m, fmaxf(fmaxf(r[i].x, r[i].y), fmaxf(r[i].z, r[i].w)));
    #pragma unroll
    for (int o = 16; o > 0; o >>= 1) m = fmaxf(m, __shfl_xor_sync(0xffffffffu, m, o));
    if ((tid & 31) == 0) sh[tid >> 5] = m;
    __syncthreads();
    float rm = sh[0];
    #pragma unroll
    for (int i = 1; i < 8; i++) rm = fmaxf(rm, sh[i]);
    __syncthreads();

    float sum = 0.f;
    #pragma unroll
    for (int i = 0; i < 4; i++) {
        r[i].x = __expf(r[i].x - rm); sum += r[i].x;
        r[i].y = __expf(r[i].y - rm); sum += r[i].y;
        r[i].z = __expf(r[i].z - rm); sum += r[i].z;
        r[i].w = __expf(r[i].w - rm); sum += r[i].w;
    }
    #pragma unroll
    for (int o = 16; o > 0; o >>= 1) sum += __shfl_xor_sync(0xffffffffu, sum, o);
    if ((tid & 31) == 0) sh[tid >> 5] = sum;
    __syncthreads();
    float tot = 0.f;
    #pragma unroll
    for (int i = 0; i < 8; i++) tot += sh[i];
    const float inv = 1.0f / tot;

    #pragma unroll
    for (int i = 0; i < 4; i++) {
        r[i].x *= inv; r[i].y *= inv; r[i].z *= inv; r[i].w *= inv;
        *reinterpret_cast<float4*>(p + i * 1024 + tid * 4) = r[i];
    }
}

// ---------------------------------------------------------------------------
// Launch
// ---------------------------------------------------------------------------
extern "C" void kernel_launch(void* const* d_in, const int* in_sizes, int n_in,
                              void* d_out, int out_size) {
    const float* x     = (const float*)d_in[0];
    const float* gamma = (const float*)d_in[1];
    const float* beta  = (const float*)d_in[2];
    const float* wq    = (const float*)d_in[3];
    const float* bq    = (const float*)d_in[4];
    const float* wk    = (const float*)d_in[5];
    const float* bk    = (const float*)d_in[6];
    const float* wv    = (const float*)d_in[7];
    const float* bv    = (const float*)d_in[8];
    const float* wp    = (const float*)d_in[9];
    const float* bp    = (const float*)d_in[10];
    float* out = (float*)d_out;

    float *xnt, *qt, *kt, *v, *s, *aot;
    cudaGetSymbolAddress((void**)&xnt, g_xnt);
    cudaGetSymbolAddress((void**)&qt,  g_qt);
    cudaGetSymbolAddress((void**)&kt,  g_kt);
    cudaGetSymbolAddress((void**)&v,   g_v);
    cudaGetSymbolAddress((void**)&s,   g_s);
    cudaGetSymbolAddress((void**)&aot, g_aot);

    const long CHW = (long)CH * HW;
    const long SHW = (long)HW * HW;

    // 1) GroupNorm + transpose -> xnT[hw][c]
    gn_t_kernel<<<BATCH * GROUPS, 256>>>(x, gamma, beta, xnt);

    // 2) Qt[hw][cout] = xnT @ Wq^T + bq(n) ; Kt likewise. (M=HW, N=CH, K=CH)
    dim3 gqk(CH / BN, HW / BM, BATCH);
    mma_gemm<1><<<gqk, 256>>>(xnt, wq, qt, bq, nullptr, HW, CH, CH,
                              CH, CH, CHW, 0, CHW, 0, 1.0f);
    mma_gemm<1><<<gqk, 256>>>(xnt, wk, kt, bk, nullptr, HW, CH, CH,
                              CH, CH, CHW, 0, CHW, 0, 1.0f);

    // 3) V[cout][hw] = Wv @ xnT^T + bv(m). (M=CH, N=HW, K=CH)
    dim3 gv(HW / BN, CH / BM, BATCH);
    mma_gemm<0><<<gv, 256>>>(wv, xnt, v, bv, nullptr, CH, HW, CH,
                             CH, CH, 0, CHW, CHW, 0, 1.0f);

    // 4) S[q][kv] = (1/16) Qt @ Kt^T. (M=HW, N=HW, K=CH)
    dim3 gs(HW / BN, HW / BM, BATCH);
    mma_gemm<0><<<gs, 256>>>(qt, kt, s, nullptr, nullptr, HW, HW, CH,
                             CH, CH, CHW, CHW, SHW, 0, 0.0625f);

    // 5) softmax rows (in place)
    softmax_kernel<<<BATCH * HW, 256>>>(s);

    // 6) AOt[q][c] = P @ V^T. (M=HW, N=CH, K=HW)
    dim3 gpv(CH / BN, HW / BM, BATCH);
    mma_gemm<0><<<gpv, 256>>>(s, v, aot, nullptr, nullptr, HW, CH, HW,
                              HW, HW, SHW, CHW, CHW, 0, 1.0f);

    // 7) out[cout][q] = Wp @ AOt^T + bp(m) + x. (M=CH, N=HW, K=CH)
    dim3 gproj(HW / BN, CH / BM, BATCH);
    mma_gemm<0><<<gproj, 256>>>(wp, aot, out, bp, x, CH, HW, CH,
                                CH, CH, 0, CHW, CHW, CHW, 1.0f);
}